// round 6
// baseline (speedup 1.0000x reference)
#include <cuda_runtime.h>
#include <cuda_bf16.h>
#include <math.h>
#include <stdint.h>

// Problem constants (fixed by setup_inputs)
#define BB 8
#define SS 1024
#define DD 1024
#define HH 16
#define HD 64
#define MM (BB * SS)       // 8192
#define TD (3 * DD)        // 3072

// Scratch: device globals (no allocation allowed)
__device__ __align__(256) float g_qkv[(size_t)MM * TD];    // [8192, 3072]
__device__ __align__(256) float g_att[(size_t)MM * DD];    // attention output (heads concat)
__device__ __align__(256) float g_proj[(size_t)MM * DD];   // proj + residual

// ---------------------------------------------------------------------------
// tf32 helpers
// ---------------------------------------------------------------------------
__device__ __forceinline__ float to_tf32(float x) {
    uint32_t o;
    asm("cvt.rna.tf32.f32 %0, %1;" : "=r"(o) : "f"(x));
    return __uint_as_float(o);
}
__device__ __forceinline__ uint32_t to_tf32_bits(float x) {
    uint32_t o;
    asm("cvt.rna.tf32.f32 %0, %1;" : "=r"(o) : "f"(x));
    return o;
}
// Split x into tf32 hi/lo floats
__device__ __forceinline__ void split_tf32_f(float x, float& hi, float& lo) {
    hi = to_tf32(x);
    lo = to_tf32(x - hi);
}

#define MMA_TF32(d, a, b)                                                     \
    asm volatile(                                                             \
        "mma.sync.aligned.m16n8k8.row.col.f32.tf32.tf32.f32 "                 \
        "{%0,%1,%2,%3}, {%4,%5,%6,%7}, {%8,%9}, {%0,%1,%2,%3};"               \
        : "+f"((d)[0]), "+f"((d)[1]), "+f"((d)[2]), "+f"((d)[3])              \
        : "r"((a)[0]), "r"((a)[1]), "r"((a)[2]), "r"((a)[3]),                 \
          "r"((b)[0]), "r"((b)[1]))

// ---------------------------------------------------------------------------
// GEMM: C[M,N] = A[M,K]*B[K,N] + bias[N] (+ res[M,N] if res != nullptr)
// fp32-accurate via tf32x3 (hi/lo split, 3 mma.sync per tile-pair).
// Hi/lo pairs stored INTERLEAVED as float2 in smem: one LDS.64 per fragment
// element fetches both operands. Split done once per element at staging.
// Block tile 128x128, K-tile 16, 256 threads (8 warps: 4 along M x 2 along N).
// ---------------------------------------------------------------------------
__global__ __launch_bounds__(256) void gemm_tf32_kernel(
    const float* __restrict__ A, const float* __restrict__ B,
    const float* __restrict__ bias, const float* __restrict__ res,
    float* __restrict__ C, int M, int N, int K)
{
    __shared__ __align__(16) float2 A2[2][16][132];  // {hi,lo} [buf][k][m] (A^T)
    __shared__ __align__(16) float2 B2[2][16][132];  // {hi,lo} [buf][k][n]

    const int tid  = threadIdx.x;
    const int lane = tid & 31;
    const int warp = tid >> 5;
    const int warp_m = warp & 3;       // 0..3 -> 32-row slice
    const int warp_n = warp >> 2;      // 0..1 -> 64-col slice
    const int g = lane >> 2;           // 0..7
    const int t = lane & 3;            // 0..3

    const int m0 = blockIdx.y * 128;
    const int n0 = blockIdx.x * 128;

    float acc[2][8][4];
    #pragma unroll
    for (int i = 0; i < 2; i++)
        #pragma unroll
        for (int j = 0; j < 8; j++)
            #pragma unroll
            for (int c = 0; c < 4; c++) acc[i][j][c] = 0.f;

    const int ra = tid >> 2;              // 0..63
    const int ca = (tid & 3) * 4;         // 0,4,8,12
    const int rb = tid >> 5;              // 0..7
    const int cb = (tid & 31) * 4;        // 0..124

    const float* pa0 = &A[(size_t)(m0 + ra) * K + ca];
    const float* pa1 = &A[(size_t)(m0 + ra + 64) * K + ca];
    const float* pb0 = &B[(size_t)rb * N + n0 + cb];
    const float* pb1 = &B[(size_t)(rb + 8) * N + n0 + cb];

    // Stage one K-tile into buffer nb (split once per element, interleaved)
    #define STAGE_TILE(nb, va0, va1, vb0, vb1)                                   \
    do {                                                                         \
        float h, l;                                                             \
        split_tf32_f((va0).x, h, l); A2[nb][ca + 0][ra] = make_float2(h, l);     \
        split_tf32_f((va0).y, h, l); A2[nb][ca + 1][ra] = make_float2(h, l);     \
        split_tf32_f((va0).z, h, l); A2[nb][ca + 2][ra] = make_float2(h, l);     \
        split_tf32_f((va0).w, h, l); A2[nb][ca + 3][ra] = make_float2(h, l);     \
        split_tf32_f((va1).x, h, l); A2[nb][ca + 0][ra + 64] = make_float2(h, l);\
        split_tf32_f((va1).y, h, l); A2[nb][ca + 1][ra + 64] = make_float2(h, l);\
        split_tf32_f((va1).z, h, l); A2[nb][ca + 2][ra + 64] = make_float2(h, l);\
        split_tf32_f((va1).w, h, l); A2[nb][ca + 3][ra + 64] = make_float2(h, l);\
        float h0, l0, h1, l1;                                                    \
        split_tf32_f((vb0).x, h0, l0); split_tf32_f((vb0).y, h1, l1);            \
        *(float4*)&B2[nb][rb][cb]     = make_float4(h0, l0, h1, l1);             \
        split_tf32_f((vb0).z, h0, l0); split_tf32_f((vb0).w, h1, l1);            \
        *(float4*)&B2[nb][rb][cb + 2] = make_float4(h0, l0, h1, l1);             \
        split_tf32_f((vb1).x, h0, l0); split_tf32_f((vb1).y, h1, l1);            \
        *(float4*)&B2[nb][rb + 8][cb]     = make_float4(h0, l0, h1, l1);         \
        split_tf32_f((vb1).z, h0, l0); split_tf32_f((vb1).w, h1, l1);            \
        *(float4*)&B2[nb][rb + 8][cb + 2] = make_float4(h0, l0, h1, l1);         \
    } while (0)

    // Preload tile 0 into buffer 0
    {
        float4 va0 = *(const float4*)pa0;
        float4 va1 = *(const float4*)pa1;
        float4 vb0 = *(const float4*)pb0;
        float4 vb1 = *(const float4*)pb1;
        STAGE_TILE(0, va0, va1, vb0, vb1);
    }
    __syncthreads();

    const int am = warp_m * 32 + g;       // A row base for this thread
    const int bn = warp_n * 64 + g;       // B col base for this thread

    int buf = 0;
    for (int k0 = 0; k0 < K; k0 += 16) {
        float4 va0, va1, vb0, vb1;
        const bool more = (k0 + 16) < K;
        if (more) {
            va0 = *(const float4*)(pa0 + k0 + 16);
            va1 = *(const float4*)(pa1 + k0 + 16);
            vb0 = *(const float4*)(pb0 + (size_t)(k0 + 16) * N);
            vb1 = *(const float4*)(pb1 + (size_t)(k0 + 16) * N);
        }

        // Mainloop: LDS.64 (hi+lo together) + MMA only
        #pragma unroll
        for (int ks = 0; ks < 16; ks += 8) {
            const int kr = ks + t;
            uint32_t aih[2][4], ail[2][4];
            #pragma unroll
            for (int mt = 0; mt < 2; mt++) {
                const int mrow = am + mt * 16;
                const float2 a0 = A2[buf][kr][mrow];
                const float2 a1 = A2[buf][kr][mrow + 8];
                const float2 a2 = A2[buf][kr + 4][mrow];
                const float2 a3 = A2[buf][kr + 4][mrow + 8];
                aih[mt][0] = __float_as_uint(a0.x); ail[mt][0] = __float_as_uint(a0.y);
                aih[mt][1] = __float_as_uint(a1.x); ail[mt][1] = __float_as_uint(a1.y);
                aih[mt][2] = __float_as_uint(a2.x); ail[mt][2] = __float_as_uint(a2.y);
                aih[mt][3] = __float_as_uint(a3.x); ail[mt][3] = __float_as_uint(a3.y);
            }
            #pragma unroll
            for (int nt = 0; nt < 8; nt++) {
                const int ncol = bn + nt * 8;
                const float2 b0 = B2[buf][kr][ncol];
                const float2 b1 = B2[buf][kr + 4][ncol];
                uint32_t bh[2], bl[2];
                bh[0] = __float_as_uint(b0.x); bl[0] = __float_as_uint(b0.y);
                bh[1] = __float_as_uint(b1.x); bl[1] = __float_as_uint(b1.y);
                #pragma unroll
                for (int mt = 0; mt < 2; mt++) {
                    MMA_TF32(acc[mt][nt], aih[mt], bh);
                    MMA_TF32(acc[mt][nt], aih[mt], bl);
                    MMA_TF32(acc[mt][nt], ail[mt], bh);
                }
            }
        }

        if (more) {
            const int nb = buf ^ 1;
            STAGE_TILE(nb, va0, va1, vb0, vb1);
        }
        __syncthreads();
        buf ^= 1;
    }
    #undef STAGE_TILE

    // Epilogue: c0/c1 -> (row, col..col+1), c2/c3 -> (row+8, col..col+1)
    #pragma unroll
    for (int mt = 0; mt < 2; mt++) {
        const int r0 = m0 + warp_m * 32 + mt * 16 + g;
        #pragma unroll
        for (int nt = 0; nt < 8; nt++) {
            const int col = n0 + warp_n * 64 + nt * 8 + t * 2;
            const float2 bv = *(const float2*)&bias[col];
            float2 v0, v1;
            v0.x = acc[mt][nt][0] + bv.x;  v0.y = acc[mt][nt][1] + bv.y;
            v1.x = acc[mt][nt][2] + bv.x;  v1.y = acc[mt][nt][3] + bv.y;
            if (res) {
                const float2 rA = *(const float2*)&res[(size_t)r0 * N + col];
                const float2 rB = *(const float2*)&res[(size_t)(r0 + 8) * N + col];
                v0.x += rA.x; v0.y += rA.y;
                v1.x += rB.x; v1.y += rB.y;
            }
            *(float2*)&C[(size_t)r0 * N + col]       = v0;
            *(float2*)&C[(size_t)(r0 + 8) * N + col] = v1;
        }
    }
}

// ---------------------------------------------------------------------------
// Tensor-core flash attention. grid = (S/64, B*H), 256 threads (8 warps).
// Q tile 64 x KV tile 64, hd = 64. Warp layout: warp_q = warp&3 (16 q-rows),
// warp_k = warp>>2 (32 kv-cols for S; 32 d-cols for PV).
// Q fragments persist in registers (tf32 pre-rounded). K/V tf32 pre-rounded
// at staging. S round-trips through smem for softmax + layout conversion.
// ---------------------------------------------------------------------------
#define QS_STRIDE 72
#define SS_STRIDE 68
#define ATTN_SMEM_FLOATS (3 * 64 * 72)

__global__ __launch_bounds__(256) void attn_kernel(
    const float* __restrict__ qkv, float* __restrict__ outp)
{
    extern __shared__ float sm[];
    float* Kt = sm;                       // [64][72]  Kt[d][kcol]
    float* Vs = sm + 64 * QS_STRIDE;      // [64][72]  Vs[kidx][d]
    float* Sp = sm + 2 * 64 * QS_STRIDE;  // Ss [64][68]; aliased as Qs [64][72] at init

    __shared__ float m_s[64], l_s[64], alpha_s[64];
    __shared__ float red[64][4];

    const int tid  = threadIdx.x;
    const int lane = tid & 31;
    const int warp = tid >> 5;
    const int warp_q = warp & 3;          // 16 q-rows
    const int warp_k = warp >> 2;         // 32 kv/d cols
    const int g = lane >> 2;              // 0..7
    const int t = lane & 3;               // 0..3

    const int qi = blockIdx.x;            // 0..15
    const int b  = blockIdx.y >> 4;
    const int h  = blockIdx.y & 15;
    const int q0 = qi * 64;
    const float scale = 0.03125f;         // 1/sqrt(1024)
    const size_t base = ((size_t)b * SS) * TD + (size_t)h * HD;

    const int am = warp_q * 16 + g;       // this thread's q-row (c0/c1); +8 for c2/c3

    // --- Stage Q (transposed, tf32-rounded) into Qs (= Sp region) ---
    #pragma unroll
    for (int i = 0; i < 4; i++) {
        int e = tid + i * 256;            // 0..1023
        int r = e >> 4, c4 = (e & 15) * 4;
        float4 v = *(const float4*)&qkv[base + (size_t)(q0 + r) * TD + c4];
        Sp[(c4 + 0) * QS_STRIDE + r] = to_tf32(v.x);
        Sp[(c4 + 1) * QS_STRIDE + r] = to_tf32(v.y);
        Sp[(c4 + 2) * QS_STRIDE + r] = to_tf32(v.z);
        Sp[(c4 + 3) * QS_STRIDE + r] = to_tf32(v.w);
    }
    if (tid < 64) { m_s[tid] = -1e30f; l_s[tid] = 0.f; }
    __syncthreads();

    // --- Q fragments into registers: 8 k8-steps x 4 regs ---
    uint32_t qf[8][4];
    #pragma unroll
    for (int ks = 0; ks < 8; ks++) {
        const int kr = ks * 8 + t;
        qf[ks][0] = __float_as_uint(Sp[kr * QS_STRIDE + am]);
        qf[ks][1] = __float_as_uint(Sp[kr * QS_STRIDE + am + 8]);
        qf[ks][2] = __float_as_uint(Sp[(kr + 4) * QS_STRIDE + am]);
        qf[ks][3] = __float_as_uint(Sp[(kr + 4) * QS_STRIDE + am + 8]);
    }

    float acc_o[4][4];
    #pragma unroll
    for (int i = 0; i < 4; i++)
        #pragma unroll
        for (int j = 0; j < 4; j++) acc_o[i][j] = 0.f;

    const int row  = tid >> 2;            // softmax row 0..63
    const int part = tid & 3;             // 16 cols each

    const int ntiles = qi + 1;
    for (int j = 0; j < ntiles; j++) {
        const int k0 = j * 64;
        __syncthreads();   // prev PV / Q-frag reads done before overwriting Kt/Vs

        // --- Stage K (transposed) and V, tf32-rounded ---
        #pragma unroll
        for (int i = 0; i < 4; i++) {
            int e = tid + i * 256;
            int r = e >> 4, c4 = (e & 15) * 4;
            const size_t gp = base + (size_t)(k0 + r) * TD + c4;
            float4 vk = *(const float4*)&qkv[gp + 1024];
            Kt[(c4 + 0) * QS_STRIDE + r] = to_tf32(vk.x);
            Kt[(c4 + 1) * QS_STRIDE + r] = to_tf32(vk.y);
            Kt[(c4 + 2) * QS_STRIDE + r] = to_tf32(vk.z);
            Kt[(c4 + 3) * QS_STRIDE + r] = to_tf32(vk.w);
            float4 vv = *(const float4*)&qkv[gp + 2048];
            float4 vr;
            vr.x = to_tf32(vv.x); vr.y = to_tf32(vv.y);
            vr.z = to_tf32(vv.z); vr.w = to_tf32(vv.w);
            *(float4*)&Vs[r * QS_STRIDE + c4] = vr;
        }
        __syncthreads();

        // --- S = Q K^T (m=q, n=kcol, k=d) ---
        float acc_s[4][4];
        #pragma unroll
        for (int nt = 0; nt < 4; nt++)
            #pragma unroll
            for (int c = 0; c < 4; c++) acc_s[nt][c] = 0.f;

        #pragma unroll
        for (int ks = 0; ks < 8; ks++) {
            const int kr = ks * 8 + t;
            #pragma unroll
            for (int nt = 0; nt < 4; nt++) {
                const int ncol = warp_k * 32 + nt * 8 + g;
                uint32_t bb[2];
                bb[0] = __float_as_uint(Kt[kr * QS_STRIDE + ncol]);
                bb[1] = __float_as_uint(Kt[(kr + 4) * QS_STRIDE + ncol]);
                MMA_TF32(acc_s[nt], qf[ks], bb);
            }
        }

        // --- Scale + causal mask -> Ss ---
        #pragma unroll
        for (int nt = 0; nt < 4; nt++) {
            const int col = warp_k * 32 + nt * 8 + t * 2;
            const int kk = k0 + col;
            const int r0 = q0 + am, r1 = r0 + 8;
            Sp[am * SS_STRIDE + col]           = (kk     <= r0) ? acc_s[nt][0] * scale : -1e30f;
            Sp[am * SS_STRIDE + col + 1]       = (kk + 1 <= r0) ? acc_s[nt][1] * scale : -1e30f;
            Sp[(am + 8) * SS_STRIDE + col]     = (kk     <= r1) ? acc_s[nt][2] * scale : -1e30f;
            Sp[(am + 8) * SS_STRIDE + col + 1] = (kk + 1 <= r1) ? acc_s[nt][3] * scale : -1e30f;
        }
        __syncthreads();

        // --- Online softmax over Ss rows ---
        {
            float pm = -1e30f;
            #pragma unroll
            for (int c = 0; c < 16; c++)
                pm = fmaxf(pm, Sp[row * SS_STRIDE + part * 16 + c]);
            red[row][part] = pm;
        }
        __syncthreads();
        if (tid < 64) {
            float tmax = fmaxf(fmaxf(red[tid][0], red[tid][1]),
                               fmaxf(red[tid][2], red[tid][3]));
            float mnew = fmaxf(m_s[tid], tmax);
            alpha_s[tid] = __expf(m_s[tid] - mnew);
            m_s[tid] = mnew;
        }
        __syncthreads();
        {
            const float mrow = m_s[row];
            float psum = 0.f;
            #pragma unroll
            for (int c = 0; c < 16; c++) {
                float p = __expf(Sp[row * SS_STRIDE + part * 16 + c] - mrow);
                Sp[row * SS_STRIDE + part * 16 + c] = p;
                psum += p;
            }
            red[row][part] = psum;
        }
        __syncthreads();
        if (tid < 64) {
            l_s[tid] = l_s[tid] * alpha_s[tid]
                     + red[tid][0] + red[tid][1] + red[tid][2] + red[tid][3];
        }

        // --- Rescale O, then O += P V (m=q, n=d, k=kidx) ---
        {
            const float al0 = alpha_s[am];
            const float al1 = alpha_s[am + 8];
            #pragma unroll
            for (int nt = 0; nt < 4; nt++) {
                acc_o[nt][0] *= al0; acc_o[nt][1] *= al0;
                acc_o[nt][2] *= al1; acc_o[nt][3] *= al1;
            }
        }
        #pragma unroll
        for (int ks = 0; ks < 8; ks++) {
            const int kr = ks * 8 + t;
            uint32_t pa[4];
            pa[0] = to_tf32_bits(Sp[am * SS_STRIDE + kr]);
            pa[1] = to_tf32_bits(Sp[(am + 8) * SS_STRIDE + kr]);
            pa[2] = to_tf32_bits(Sp[am * SS_STRIDE + kr + 4]);
            pa[3] = to_tf32_bits(Sp[(am + 8) * SS_STRIDE + kr + 4]);
            #pragma unroll
            for (int nt = 0; nt < 4; nt++) {
                const int ncol = warp_k * 32 + nt * 8 + g;
                uint32_t bb[2];
                bb[0] = __float_as_uint(Vs[kr * QS_STRIDE + ncol]);
                bb[1] = __float_as_uint(Vs[(kr + 4) * QS_STRIDE + ncol]);
                MMA_TF32(acc_o[nt], pa, bb);
            }
        }
    }

    __syncthreads();   // l_s final before reads
    // --- Normalize and write: out[B,S, h*64 + d] ---
    {
        const float inv0 = 1.0f / l_s[am];
        const float inv1 = 1.0f / l_s[am + 8];
        #pragma unroll
        for (int nt = 0; nt < 4; nt++) {
            const int col = h * HD + warp_k * 32 + nt * 8 + t * 2;
            const size_t r0 = (size_t)(b * SS + q0 + am) * DD + col;
            const size_t r1 = (size_t)(b * SS + q0 + am + 8) * DD + col;
            float2 v0, v1;
            v0.x = acc_o[nt][0] * inv0; v0.y = acc_o[nt][1] * inv0;
            v1.x = acc_o[nt][2] * inv1; v1.y = acc_o[nt][3] * inv1;
            *(float2*)&outp[r0] = v0;
            *(float2*)&outp[r1] = v1;
        }
    }
}

// ---------------------------------------------------------------------------
// LayerNorm over last dim (1024). One block per row, 256 threads x 4 floats.
// ---------------------------------------------------------------------------
__global__ __launch_bounds__(256) void ln_kernel(
    const float* __restrict__ in, const float* __restrict__ gamma,
    const float* __restrict__ beta, float* __restrict__ out)
{
    int r = blockIdx.x;
    int tid = threadIdx.x;
    const float4 v = ((const float4*)(in + (size_t)r * DD))[tid];
    float s  = v.x + v.y + v.z + v.w;
    float sq = v.x * v.x + v.y * v.y + v.z * v.z + v.w * v.w;

    __shared__ float rs[8], rq[8];
    __shared__ float mu_s, rstd_s;
    #pragma unroll
    for (int off = 16; off > 0; off >>= 1) {
        s  += __shfl_down_sync(0xffffffffu, s, off);
        sq += __shfl_down_sync(0xffffffffu, sq, off);
    }
    if ((tid & 31) == 0) { rs[tid >> 5] = s; rq[tid >> 5] = sq; }
    __syncthreads();
    if (tid == 0) {
        float S = 0.f, Q = 0.f;
        #pragma unroll
        for (int i = 0; i < 8; i++) { S += rs[i]; Q += rq[i]; }
        float mu = S * (1.0f / DD);
        float var = Q * (1.0f / DD) - mu * mu;
        mu_s = mu;
        rstd_s = rsqrtf(var + 1e-5f);
    }
    __syncthreads();
    float mu = mu_s, rstd = rstd_s;
    const float4 gm = ((const float4*)gamma)[tid];
    const float4 be = ((const float4*)beta)[tid];
    float4 o;
    o.x = (v.x - mu) * rstd * gm.x + be.x;
    o.y = (v.y - mu) * rstd * gm.y + be.y;
    o.z = (v.z - mu) * rstd * gm.z + be.z;
    o.w = (v.w - mu) * rstd * gm.w + be.w;
    ((float4*)(out + (size_t)r * DD))[tid] = o;
}

// ---------------------------------------------------------------------------
extern "C" void kernel_launch(void* const* d_in, const int* in_sizes, int n_in,
                              void* d_out, int out_size)
{
    const float* x     = (const float*)d_in[0];
    const float* Wqkv  = (const float*)d_in[1];
    const float* bqkv  = (const float*)d_in[2];
    const float* Wout  = (const float*)d_in[3];
    const float* bout  = (const float*)d_in[4];
    const float* gamma = (const float*)d_in[5];
    const float* beta  = (const float*)d_in[6];
    float* out = (float*)d_out;

    float *qkv_p, *att_p, *proj_p;
    cudaGetSymbolAddress((void**)&qkv_p,  g_qkv);
    cudaGetSymbolAddress((void**)&att_p,  g_att);
    cudaGetSymbolAddress((void**)&proj_p, g_proj);

    // 1. QKV projection (tf32x3 tensor cores, interleaved hi/lo smem)
    {
        dim3 grid(TD / 128, MM / 128);
        gemm_tf32_kernel<<<grid, 256>>>(x, Wqkv, bqkv, nullptr, qkv_p, MM, TD, DD);
    }
    // 2. Causal multi-head attention (tf32 tensor cores)
    {
        const int smem_bytes = ATTN_SMEM_FLOATS * (int)sizeof(float);
        cudaFuncSetAttribute(attn_kernel,
                             cudaFuncAttributeMaxDynamicSharedMemorySize,
                             smem_bytes);
        dim3 grid(SS / 64, BB * HH);
        attn_kernel<<<grid, 256, smem_bytes>>>(qkv_p, att_p);
    }
    // 3. Output projection + residual (tf32x3 tensor cores)
    {
        dim3 grid(DD / 128, MM / 128);
        gemm_tf32_kernel<<<grid, 256>>>(att_p, Wout, bout, x, proj_p, MM, DD, DD);
    }
    // 4. LayerNorm
    ln_kernel<<<MM, 256>>>(proj_p, gamma, beta, out);
}

// round 16
// speedup vs baseline: 2.2952x; 2.2952x over previous
#include <cuda_runtime.h>
#include <cuda_bf16.h>
#include <math.h>
#include <stdint.h>

// Problem constants (fixed by setup_inputs)
#define BB 8
#define SS 1024
#define DD 1024
#define HH 16
#define HD 64
#define MM (BB * SS)       // 8192
#define TD (3 * DD)        // 3072

// Scratch: device globals (no allocation allowed)
__device__ __align__(256) float g_qkv[(size_t)MM * TD];    // [8192, 3072]
__device__ __align__(256) float g_att[(size_t)MM * DD];    // attention output (heads concat)
__device__ __align__(256) float g_proj[(size_t)MM * DD];   // proj + residual

// ---------------------------------------------------------------------------
// tf32 helpers
// ---------------------------------------------------------------------------
__device__ __forceinline__ float to_tf32(float x) {
    uint32_t o;
    asm("cvt.rna.tf32.f32 %0, %1;" : "=r"(o) : "f"(x));
    return __uint_as_float(o);
}
__device__ __forceinline__ uint32_t to_tf32_bits(float x) {
    uint32_t o;
    asm("cvt.rna.tf32.f32 %0, %1;" : "=r"(o) : "f"(x));
    return o;
}

#define MMA_TF32(d, a, b)                                                     \
    asm volatile(                                                             \
        "mma.sync.aligned.m16n8k8.row.col.f32.tf32.tf32.f32 "                 \
        "{%0,%1,%2,%3}, {%4,%5,%6,%7}, {%8,%9}, {%0,%1,%2,%3};"               \
        : "+f"((d)[0]), "+f"((d)[1]), "+f"((d)[2]), "+f"((d)[3])              \
        : "r"((a)[0]), "r"((a)[1]), "r"((a)[2]), "r"((a)[3]),                 \
          "r"((b)[0]), "r"((b)[1]))

// ---------------------------------------------------------------------------
// GEMM: C[M,N] = A[M,K]*B[K,N] + bias[N] (+ res[M,N] if res != nullptr)
// SINGLE-PASS tf32 (operands rounded to tf32 once at staging; 1 mma per
// tile-pair). Block tile 128x128, K-tile 16, 256 threads
// (8 warps: 4 along M x 2 along N). Warp tile 32x64. Double-buffered smem,
// register prefetch, 1 barrier / K-tile. Rows padded to 132 -> conflict-free.
// ---------------------------------------------------------------------------
__global__ __launch_bounds__(256) void gemm_tf32_kernel(
    const float* __restrict__ A, const float* __restrict__ B,
    const float* __restrict__ bias, const float* __restrict__ res,
    float* __restrict__ C, int M, int N, int K)
{
    __shared__ float As[2][16][132];   // tf32 [buf][k][m] (A transposed)
    __shared__ float Bs[2][16][132];   // tf32 [buf][k][n]

    const int tid  = threadIdx.x;
    const int lane = tid & 31;
    const int warp = tid >> 5;
    const int warp_m = warp & 3;       // 0..3 -> 32-row slice
    const int warp_n = warp >> 2;      // 0..1 -> 64-col slice
    const int g = lane >> 2;           // 0..7
    const int t = lane & 3;            // 0..3

    const int m0 = blockIdx.y * 128;
    const int n0 = blockIdx.x * 128;

    float acc[2][8][4];
    #pragma unroll
    for (int i = 0; i < 2; i++)
        #pragma unroll
        for (int j = 0; j < 8; j++)
            #pragma unroll
            for (int c = 0; c < 4; c++) acc[i][j][c] = 0.f;

    const int ra = tid >> 2;              // 0..63
    const int ca = (tid & 3) * 4;         // 0,4,8,12
    const int rb = tid >> 5;              // 0..7
    const int cb = (tid & 31) * 4;        // 0..124

    const float* pa0 = &A[(size_t)(m0 + ra) * K + ca];
    const float* pa1 = &A[(size_t)(m0 + ra + 64) * K + ca];
    const float* pb0 = &B[(size_t)rb * N + n0 + cb];
    const float* pb1 = &B[(size_t)(rb + 8) * N + n0 + cb];

    #define STAGE_TILE(nb, va0, va1, vb0, vb1)                                   \
    do {                                                                         \
        As[nb][ca + 0][ra] = to_tf32((va0).x);                                   \
        As[nb][ca + 1][ra] = to_tf32((va0).y);                                   \
        As[nb][ca + 2][ra] = to_tf32((va0).z);                                   \
        As[nb][ca + 3][ra] = to_tf32((va0).w);                                   \
        As[nb][ca + 0][ra + 64] = to_tf32((va1).x);                              \
        As[nb][ca + 1][ra + 64] = to_tf32((va1).y);                              \
        As[nb][ca + 2][ra + 64] = to_tf32((va1).z);                              \
        As[nb][ca + 3][ra + 64] = to_tf32((va1).w);                              \
        float4 bt0, bt1;                                                         \
        bt0.x = to_tf32((vb0).x); bt0.y = to_tf32((vb0).y);                      \
        bt0.z = to_tf32((vb0).z); bt0.w = to_tf32((vb0).w);                      \
        bt1.x = to_tf32((vb1).x); bt1.y = to_tf32((vb1).y);                      \
        bt1.z = to_tf32((vb1).z); bt1.w = to_tf32((vb1).w);                      \
        *(float4*)&Bs[nb][rb][cb]     = bt0;                                     \
        *(float4*)&Bs[nb][rb + 8][cb] = bt1;                                     \
    } while (0)

    // Preload tile 0 into buffer 0
    {
        float4 va0 = *(const float4*)pa0;
        float4 va1 = *(const float4*)pa1;
        float4 vb0 = *(const float4*)pb0;
        float4 vb1 = *(const float4*)pb1;
        STAGE_TILE(0, va0, va1, vb0, vb1);
    }
    __syncthreads();

    const int am = warp_m * 32 + g;       // A row base for this thread
    const int bn = warp_n * 64 + g;       // B col base for this thread

    int buf = 0;
    for (int k0 = 0; k0 < K; k0 += 16) {
        float4 va0, va1, vb0, vb1;
        const bool more = (k0 + 16) < K;
        if (more) {
            va0 = *(const float4*)(pa0 + k0 + 16);
            va1 = *(const float4*)(pa1 + k0 + 16);
            vb0 = *(const float4*)(pb0 + (size_t)(k0 + 16) * N);
            vb1 = *(const float4*)(pb1 + (size_t)(k0 + 16) * N);
        }

        // Mainloop: pure LDS + MMA (single tf32 pass)
        #pragma unroll
        for (int ks = 0; ks < 16; ks += 8) {
            const int kr = ks + t;
            uint32_t af[2][4];
            #pragma unroll
            for (int mt = 0; mt < 2; mt++) {
                const int mrow = am + mt * 16;
                af[mt][0] = __float_as_uint(As[buf][kr][mrow]);
                af[mt][1] = __float_as_uint(As[buf][kr][mrow + 8]);
                af[mt][2] = __float_as_uint(As[buf][kr + 4][mrow]);
                af[mt][3] = __float_as_uint(As[buf][kr + 4][mrow + 8]);
            }
            #pragma unroll
            for (int nt = 0; nt < 8; nt++) {
                const int ncol = bn + nt * 8;
                uint32_t bf[2];
                bf[0] = __float_as_uint(Bs[buf][kr][ncol]);
                bf[1] = __float_as_uint(Bs[buf][kr + 4][ncol]);
                #pragma unroll
                for (int mt = 0; mt < 2; mt++) {
                    MMA_TF32(acc[mt][nt], af[mt], bf);
                }
            }
        }

        if (more) {
            const int nb = buf ^ 1;
            STAGE_TILE(nb, va0, va1, vb0, vb1);
        }
        __syncthreads();
        buf ^= 1;
    }
    #undef STAGE_TILE

    // Epilogue: c0/c1 -> (row, col..col+1), c2/c3 -> (row+8, col..col+1)
    #pragma unroll
    for (int mt = 0; mt < 2; mt++) {
        const int r0 = m0 + warp_m * 32 + mt * 16 + g;
        #pragma unroll
        for (int nt = 0; nt < 8; nt++) {
            const int col = n0 + warp_n * 64 + nt * 8 + t * 2;
            const float2 bv = *(const float2*)&bias[col];
            float2 v0, v1;
            v0.x = acc[mt][nt][0] + bv.x;  v0.y = acc[mt][nt][1] + bv.y;
            v1.x = acc[mt][nt][2] + bv.x;  v1.y = acc[mt][nt][3] + bv.y;
            if (res) {
                const float2 rA = *(const float2*)&res[(size_t)r0 * N + col];
                const float2 rB = *(const float2*)&res[(size_t)(r0 + 8) * N + col];
                v0.x += rA.x; v0.y += rA.y;
                v1.x += rB.x; v1.y += rB.y;
            }
            *(float2*)&C[(size_t)r0 * N + col]       = v0;
            *(float2*)&C[(size_t)(r0 + 8) * N + col] = v1;
        }
    }
}

// ---------------------------------------------------------------------------
// Tensor-core flash attention. grid = (S/64, B*H), 256 threads (8 warps).
// Q tile 64 x KV tile 64, hd = 64. Warp layout: warp_q = warp&3 (16 q-rows),
// warp_k = warp>>2 (32 kv-cols for S; 32 d-cols for PV).
// Q fragments persist in registers (tf32 pre-rounded). K/V tf32 pre-rounded
// at staging. S round-trips through smem for softmax + layout conversion.
// ---------------------------------------------------------------------------
#define QS_STRIDE 72
#define SS_STRIDE 68
#define ATTN_SMEM_FLOATS (3 * 64 * 72)

__global__ __launch_bounds__(256) void attn_kernel(
    const float* __restrict__ qkv, float* __restrict__ outp)
{
    extern __shared__ float sm[];
    float* Kt = sm;                       // [64][72]  Kt[d][kcol]
    float* Vs = sm + 64 * QS_STRIDE;      // [64][72]  Vs[kidx][d]
    float* Sp = sm + 2 * 64 * QS_STRIDE;  // Ss [64][68]; aliased as Qs [64][72] at init

    __shared__ float m_s[64], l_s[64], alpha_s[64];
    __shared__ float red[64][4];

    const int tid  = threadIdx.x;
    const int lane = tid & 31;
    const int warp = tid >> 5;
    const int warp_q = warp & 3;          // 16 q-rows
    const int warp_k = warp >> 2;         // 32 kv/d cols
    const int g = lane >> 2;              // 0..7
    const int t = lane & 3;               // 0..3

    const int qi = blockIdx.x;            // 0..15
    const int b  = blockIdx.y >> 4;
    const int h  = blockIdx.y & 15;
    const int q0 = qi * 64;
    const float scale = 0.03125f;         // 1/sqrt(1024)
    const size_t base = ((size_t)b * SS) * TD + (size_t)h * HD;

    const int am = warp_q * 16 + g;       // this thread's q-row (c0/c1); +8 for c2/c3

    // --- Stage Q (transposed, tf32-rounded) into Qs (= Sp region) ---
    #pragma unroll
    for (int i = 0; i < 4; i++) {
        int e = tid + i * 256;            // 0..1023
        int r = e >> 4, c4 = (e & 15) * 4;
        float4 v = *(const float4*)&qkv[base + (size_t)(q0 + r) * TD + c4];
        Sp[(c4 + 0) * QS_STRIDE + r] = to_tf32(v.x);
        Sp[(c4 + 1) * QS_STRIDE + r] = to_tf32(v.y);
        Sp[(c4 + 2) * QS_STRIDE + r] = to_tf32(v.z);
        Sp[(c4 + 3) * QS_STRIDE + r] = to_tf32(v.w);
    }
    if (tid < 64) { m_s[tid] = -1e30f; l_s[tid] = 0.f; }
    __syncthreads();

    // --- Q fragments into registers: 8 k8-steps x 4 regs ---
    uint32_t qf[8][4];
    #pragma unroll
    for (int ks = 0; ks < 8; ks++) {
        const int kr = ks * 8 + t;
        qf[ks][0] = __float_as_uint(Sp[kr * QS_STRIDE + am]);
        qf[ks][1] = __float_as_uint(Sp[kr * QS_STRIDE + am + 8]);
        qf[ks][2] = __float_as_uint(Sp[(kr + 4) * QS_STRIDE + am]);
        qf[ks][3] = __float_as_uint(Sp[(kr + 4) * QS_STRIDE + am + 8]);
    }

    float acc_o[4][4];
    #pragma unroll
    for (int i = 0; i < 4; i++)
        #pragma unroll
        for (int j = 0; j < 4; j++) acc_o[i][j] = 0.f;

    const int row  = tid >> 2;            // softmax row 0..63
    const int part = tid & 3;             // 16 cols each

    const int ntiles = qi + 1;
    for (int j = 0; j < ntiles; j++) {
        const int k0 = j * 64;
        __syncthreads();   // prev PV / Q-frag reads done before overwriting Kt/Vs

        // --- Stage K (transposed) and V, tf32-rounded ---
        #pragma unroll
        for (int i = 0; i < 4; i++) {
            int e = tid + i * 256;
            int r = e >> 4, c4 = (e & 15) * 4;
            const size_t gp = base + (size_t)(k0 + r) * TD + c4;
            float4 vk = *(const float4*)&qkv[gp + 1024];
            Kt[(c4 + 0) * QS_STRIDE + r] = to_tf32(vk.x);
            Kt[(c4 + 1) * QS_STRIDE + r] = to_tf32(vk.y);
            Kt[(c4 + 2) * QS_STRIDE + r] = to_tf32(vk.z);
            Kt[(c4 + 3) * QS_STRIDE + r] = to_tf32(vk.w);
            float4 vv = *(const float4*)&qkv[gp + 2048];
            float4 vr;
            vr.x = to_tf32(vv.x); vr.y = to_tf32(vv.y);
            vr.z = to_tf32(vv.z); vr.w = to_tf32(vv.w);
            *(float4*)&Vs[r * QS_STRIDE + c4] = vr;
        }
        __syncthreads();

        // --- S = Q K^T (m=q, n=kcol, k=d) ---
        float acc_s[4][4];
        #pragma unroll
        for (int nt = 0; nt < 4; nt++)
            #pragma unroll
            for (int c = 0; c < 4; c++) acc_s[nt][c] = 0.f;

        #pragma unroll
        for (int ks = 0; ks < 8; ks++) {
            const int kr = ks * 8 + t;
            #pragma unroll
            for (int nt = 0; nt < 4; nt++) {
                const int ncol = warp_k * 32 + nt * 8 + g;
                uint32_t bb[2];
                bb[0] = __float_as_uint(Kt[kr * QS_STRIDE + ncol]);
                bb[1] = __float_as_uint(Kt[(kr + 4) * QS_STRIDE + ncol]);
                MMA_TF32(acc_s[nt], qf[ks], bb);
            }
        }

        // --- Scale + causal mask -> Ss ---
        #pragma unroll
        for (int nt = 0; nt < 4; nt++) {
            const int col = warp_k * 32 + nt * 8 + t * 2;
            const int kk = k0 + col;
            const int r0 = q0 + am, r1 = r0 + 8;
            Sp[am * SS_STRIDE + col]           = (kk     <= r0) ? acc_s[nt][0] * scale : -1e30f;
            Sp[am * SS_STRIDE + col + 1]       = (kk + 1 <= r0) ? acc_s[nt][1] * scale : -1e30f;
            Sp[(am + 8) * SS_STRIDE + col]     = (kk     <= r1) ? acc_s[nt][2] * scale : -1e30f;
            Sp[(am + 8) * SS_STRIDE + col + 1] = (kk + 1 <= r1) ? acc_s[nt][3] * scale : -1e30f;
        }
        __syncthreads();

        // --- Online softmax over Ss rows ---
        {
            float pm = -1e30f;
            #pragma unroll
            for (int c = 0; c < 16; c++)
                pm = fmaxf(pm, Sp[row * SS_STRIDE + part * 16 + c]);
            red[row][part] = pm;
        }
        __syncthreads();
        if (tid < 64) {
            float tmax = fmaxf(fmaxf(red[tid][0], red[tid][1]),
                               fmaxf(red[tid][2], red[tid][3]));
            float mnew = fmaxf(m_s[tid], tmax);
            alpha_s[tid] = __expf(m_s[tid] - mnew);
            m_s[tid] = mnew;
        }
        __syncthreads();
        {
            const float mrow = m_s[row];
            float psum = 0.f;
            #pragma unroll
            for (int c = 0; c < 16; c++) {
                float p = __expf(Sp[row * SS_STRIDE + part * 16 + c] - mrow);
                Sp[row * SS_STRIDE + part * 16 + c] = p;
                psum += p;
            }
            red[row][part] = psum;
        }
        __syncthreads();
        if (tid < 64) {
            l_s[tid] = l_s[tid] * alpha_s[tid]
                     + red[tid][0] + red[tid][1] + red[tid][2] + red[tid][3];
        }

        // --- Rescale O, then O += P V (m=q, n=d, k=kidx) ---
        {
            const float al0 = alpha_s[am];
            const float al1 = alpha_s[am + 8];
            #pragma unroll
            for (int nt = 0; nt < 4; nt++) {
                acc_o[nt][0] *= al0; acc_o[nt][1] *= al0;
                acc_o[nt][2] *= al1; acc_o[nt][3] *= al1;
            }
        }
        #pragma unroll
        for (int ks = 0; ks < 8; ks++) {
            const int kr = ks * 8 + t;
            uint32_t pa[4];
            pa[0] = to_tf32_bits(Sp[am * SS_STRIDE + kr]);
            pa[1] = to_tf32_bits(Sp[(am + 8) * SS_STRIDE + kr]);
            pa[2] = to_tf32_bits(Sp[am * SS_STRIDE + kr + 4]);
            pa[3] = to_tf32_bits(Sp[(am + 8) * SS_STRIDE + kr + 4]);
            #pragma unroll
            for (int nt = 0; nt < 4; nt++) {
                const int ncol = warp_k * 32 + nt * 8 + g;
                uint32_t bb[2];
                bb[0] = __float_as_uint(Vs[kr * QS_STRIDE + ncol]);
                bb[1] = __float_as_uint(Vs[(kr + 4) * QS_STRIDE + ncol]);
                MMA_TF32(acc_o[nt], pa, bb);
            }
        }
    }

    __syncthreads();   // l_s final before reads
    // --- Normalize and write: out[B,S, h*64 + d] ---
    {
        const float inv0 = 1.0f / l_s[am];
        const float inv1 = 1.0f / l_s[am + 8];
        #pragma unroll
        for (int nt = 0; nt < 4; nt++) {
            const int col = h * HD + warp_k * 32 + nt * 8 + t * 2;
            const size_t r0 = (size_t)(b * SS + q0 + am) * DD + col;
            const size_t r1 = (size_t)(b * SS + q0 + am + 8) * DD + col;
            float2 v0, v1;
            v0.x = acc_o[nt][0] * inv0; v0.y = acc_o[nt][1] * inv0;
            v1.x = acc_o[nt][2] * inv1; v1.y = acc_o[nt][3] * inv1;
            *(float2*)&outp[r0] = v0;
            *(float2*)&outp[r1] = v1;
        }
    }
}

// ---------------------------------------------------------------------------
// LayerNorm over last dim (1024). One block per row, 256 threads x 4 floats.
// ---------------------------------------------------------------------------
__global__ __launch_bounds__(256) void ln_kernel(
    const float* __restrict__ in, const float* __restrict__ gamma,
    const float* __restrict__ beta, float* __restrict__ out)
{
    int r = blockIdx.x;
    int tid = threadIdx.x;
    const float4 v = ((const float4*)(in + (size_t)r * DD))[tid];
    float s  = v.x + v.y + v.z + v.w;
    float sq = v.x * v.x + v.y * v.y + v.z * v.z + v.w * v.w;

    __shared__ float rs[8], rq[8];
    __shared__ float mu_s, rstd_s;
    #pragma unroll
    for (int off = 16; off > 0; off >>= 1) {
        s  += __shfl_down_sync(0xffffffffu, s, off);
        sq += __shfl_down_sync(0xffffffffu, sq, off);
    }
    if ((tid & 31) == 0) { rs[tid >> 5] = s; rq[tid >> 5] = sq; }
    __syncthreads();
    if (tid == 0) {
        float S = 0.f, Q = 0.f;
        #pragma unroll
        for (int i = 0; i < 8; i++) { S += rs[i]; Q += rq[i]; }
        float mu = S * (1.0f / DD);
        float var = Q * (1.0f / DD) - mu * mu;
        mu_s = mu;
        rstd_s = rsqrtf(var + 1e-5f);
    }
    __syncthreads();
    float mu = mu_s, rstd = rstd_s;
    const float4 gm = ((const float4*)gamma)[tid];
    const float4 be = ((const float4*)beta)[tid];
    float4 o;
    o.x = (v.x - mu) * rstd * gm.x + be.x;
    o.y = (v.y - mu) * rstd * gm.y + be.y;
    o.z = (v.z - mu) * rstd * gm.z + be.z;
    o.w = (v.w - mu) * rstd * gm.w + be.w;
    ((float4*)(out + (size_t)r * DD))[tid] = o;
}

// ---------------------------------------------------------------------------
extern "C" void kernel_launch(void* const* d_in, const int* in_sizes, int n_in,
                              void* d_out, int out_size)
{
    const float* x     = (const float*)d_in[0];
    const float* Wqkv  = (const float*)d_in[1];
    const float* bqkv  = (const float*)d_in[2];
    const float* Wout  = (const float*)d_in[3];
    const float* bout  = (const float*)d_in[4];
    const float* gamma = (const float*)d_in[5];
    const float* beta  = (const float*)d_in[6];
    float* out = (float*)d_out;

    float *qkv_p, *att_p, *proj_p;
    cudaGetSymbolAddress((void**)&qkv_p,  g_qkv);
    cudaGetSymbolAddress((void**)&att_p,  g_att);
    cudaGetSymbolAddress((void**)&proj_p, g_proj);

    // 1. QKV projection (single-pass tf32 tensor cores)
    {
        dim3 grid(TD / 128, MM / 128);
        gemm_tf32_kernel<<<grid, 256>>>(x, Wqkv, bqkv, nullptr, qkv_p, MM, TD, DD);
    }
    // 2. Causal multi-head attention (tf32 tensor cores)
    {
        const int smem_bytes = ATTN_SMEM_FLOATS * (int)sizeof(float);
        cudaFuncSetAttribute(attn_kernel,
                             cudaFuncAttributeMaxDynamicSharedMemorySize,
                             smem_bytes);
        dim3 grid(SS / 64, BB * HH);
        attn_kernel<<<grid, 256, smem_bytes>>>(qkv_p, att_p);
    }
    // 3. Output projection + residual (single-pass tf32 tensor cores)
    {
        dim3 grid(DD / 128, MM / 128);
        gemm_tf32_kernel<<<grid, 256>>>(att_p, Wout, bout, x, proj_p, MM, DD, DD);
    }
    // 4. LayerNorm
    ln_kernel<<<MM, 256>>>(proj_p, gamma, beta, out);
}